// round 7
// baseline (speedup 1.0000x reference)
#include <cuda_runtime.h>
#include <cstdint>

constexpr int B = 64;
constexpr int T = 1024;
constexpr int V = 512;
constexpr int L = 128;
constexpr int DP = 5;            // emit LDG register pipeline depth (rows ahead)

#define NEG2   (-1.44269504e30f)     // -1e30 in log2 domain
#define LOG2E  1.4426950408889634f
#define LN2    0.6931471805599453f
#define FULLM  0xffffffffu

__device__ float g_loss[B];
__device__ int   g_ctr = 0;

__device__ __forceinline__ float ex2f(float x) {
    float y; asm("ex2.approx.f32 %0, %1;" : "=f"(y) : "f"(x)); return y;
}
__device__ __forceinline__ float lg2f(float x) {
    float y; asm("lg2.approx.f32 %0, %1;" : "=f"(y) : "f"(x)); return y;
}
// 2-way lse (log2 domain): 2 MUFU
__device__ __forceinline__ float lse2(float a, float b) {
    const float m  = fmaxf(a, b);
    const float mn = fminf(a, b);
    return m + lg2f(1.0f + ex2f(mn - m));
}
// 3-way lse, sorted form: 2 ex2 + 1 lg2 = 3 MUFU
__device__ __forceinline__ float lse3s(float x, float y, float z) {
    const float hi = fmaxf(x, y);
    const float lo = fminf(x, y);
    const float m  = fmaxf(hi, z);
    const float t2 = fminf(hi, z);
    return m + lg2f(1.0f + ex2f(t2 - m) + ex2f(lo - m));
}

__global__ __launch_bounds__(32, 1)
void ctc_warp_kernel(const float* __restrict__ outputs,
                     const int*   __restrict__ labels,
                     const int*   __restrict__ output_lengths,
                     const int*   __restrict__ label_lengths,
                     float* __restrict__ out) {
    __shared__ float fin[2];

    const int b    = blockIdx.x;
    const int lane = threadIdx.x;

    const int olen = output_lengths[b];
    const int llen = label_lengths[b];
    const int tcap = olen - 1;
    const int s0g  = 2 * llen - 1;           // odd state
    const int s1g  = 2 * llen;               // even state (or 256)

    // labels owned by this lane: indices 4l .. 4l+3
    const int* lb = labels + b * L;
    int col[4]; bool skp[4];
    #pragma unroll
    for (int j = 0; j < 4; ++j) {
        const int li = 4 * lane + j;
        col[j] = __ldg(lb + li);
        skp[j] = (li > 0) && (col[j] != __ldg(lb + li - 1));
    }

    // capture ownership (odd states -> cap0 candidates; even -> cap1)
    bool o0[4], o1[4];
    #pragma unroll
    for (int j = 0; j < 4; ++j) {
        o0[j] = (s0g == 8 * lane + 2 * j + 1);
        o1[j] = (s1g == 8 * lane + 2 * j);
    }
    const bool oC = (lane == 31) && (s1g == 256);

    // ---- emit register pipeline: slot s holds row (t) with t % DP == s ----
    const float* gb = outputs + (size_t)b * T * V;
    float eb[DP];        // blank emit (col 0)
    float el[DP][4];     // label emits
    #pragma unroll
    for (int k = 0; k < DP; ++k) {
        const float* rp = gb + (size_t)k * V;
        eb[k] = __ldg(rp) * LOG2E;
        #pragma unroll
        for (int j = 0; j < 4; ++j) el[k][j] = __ldg(rp + col[j]) * LOG2E;
    }

    // ---- t = 0 ----
    float a[8];
    #pragma unroll
    for (int i = 0; i < 8; ++i) a[i] = NEG2;
    if (lane == 0) { a[0] = eb[0]; a[1] = el[0][0]; }
    float C = NEG2;
    float cap0 = NEG2, cap1 = NEG2;
    {
        const bool pc = (tcap == 0);
        #pragma unroll
        for (int j = 0; j < 4; ++j) {
            cap0 = (pc && o0[j]) ? a[2 * j + 1] : cap0;
            cap1 = (pc && o1[j]) ? a[2 * j]     : cap1;
        }
        cap1 = (pc && oC) ? C : cap1;
    }
    // refill slot 0 with row DP
    {
        const float* rp = gb + (size_t)DP * V;
        eb[0] = __ldg(rp) * LOG2E;
        #pragma unroll
        for (int j = 0; j < 4; ++j) el[0][j] = __ldg(rp + col[j]) * LOG2E;
    }

    // ---- main recursion: t = 1 .. (overshoot to 1025 is harmless) ----
    for (int tb = 1; tb < T; tb += DP) {
        #pragma unroll
        for (int k = 0; k < DP; ++k) {
            const int t  = tb + k;
            const int ph = (k + 1) % DP;          // slot of row t (tb % DP == 1)

            // boundary: prev lane's old a[7]
            float b7 = __shfl_up_sync(FULLM, a[7], 1);
            b7 = (lane == 0) ? NEG2 : b7;

            const float ebc = eb[ph];

            // state 256 (lane 31; uses old a[7] = alpha[255])
            C = lse2(C, a[7]) + ebc;

            // descending in-place update: reads old lower-index values
            a[7] = lse3s(a[7], a[6], skp[3] ? a[5] : NEG2) + el[ph][3];
            a[6] = lse2 (a[6], a[5]) + ebc;
            a[5] = lse3s(a[5], a[4], skp[2] ? a[3] : NEG2) + el[ph][2];
            a[4] = lse2 (a[4], a[3]) + ebc;
            a[3] = lse3s(a[3], a[2], skp[1] ? a[1] : NEG2) + el[ph][1];
            a[2] = lse2 (a[2], a[1]) + ebc;
            a[1] = lse3s(a[1], a[0], skp[0] ? b7 : NEG2) + el[ph][0];
            a[0] = lse2 (a[0], b7) + ebc;

            // branch-free captures
            const bool pc = (t == tcap);
            #pragma unroll
            for (int j = 0; j < 4; ++j) {
                cap0 = (pc && o0[j]) ? a[2 * j + 1] : cap0;
                cap1 = (pc && o1[j]) ? a[2 * j]     : cap1;
            }
            cap1 = (pc && oC) ? C : cap1;

            // refill slot ph with row t + DP (clamped; overshoot rows unused)
            int tr = t + DP; tr = (tr < T) ? tr : (T - 1);
            const float* rp = gb + (size_t)tr * V;
            eb[ph] = __ldg(rp) * LOG2E;
            #pragma unroll
            for (int j = 0; j < 4; ++j) el[ph][j] = __ldg(rp + col[j]) * LOG2E;
        }
    }

    // ---- finish ----
    const bool own0 = o0[0] || o0[1] || o0[2] || o0[3];
    const bool own1 = o1[0] || o1[1] || o1[2] || o1[3] || oC;
    if (own0) fin[0] = cap0;
    if (own1) fin[1] = cap1;
    __syncwarp();

    if (lane == 0) {
        const float ll = lse2(fin[0], fin[1]) * LN2;
        g_loss[b] = -ll / (float)llen;
        __threadfence();
        const int old = atomicAdd(&g_ctr, 1);
        if (old == B - 1) {
            __threadfence();
            float s = 0.0f;
            #pragma unroll 8
            for (int i = 0; i < B; ++i) s += g_loss[i];
            *out = s * (1.0f / (float)B);
            g_ctr = 0;   // reset for next graph replay
        }
    }
}

extern "C" void kernel_launch(void* const* d_in, const int* in_sizes, int n_in,
                              void* d_out, int out_size) {
    const float* outputs        = (const float*)d_in[0];
    const int*   labels         = (const int*)d_in[1];
    const int*   output_lengths = (const int*)d_in[2];
    const int*   label_lengths  = (const int*)d_in[3];
    float* out = (float*)d_out;

    ctc_warp_kernel<<<B, 32>>>(outputs, labels, output_lengths,
                               label_lengths, out);
}

// round 9
// speedup vs baseline: 2.2817x; 2.2817x over previous
#include <cuda_runtime.h>
#include <cstdint>

constexpr int B = 64;
constexpr int T = 1024;
constexpr int V = 512;
constexpr int L = 128;
constexpr int EST = 132;     // emit row stride (floats): [lab0..lab127, blank, pad3]
constexpr int DP  = 4;       // emit lookahead (= renorm block size)

#define FULLM  0xffffffffu
#define LOG2E  1.4426950408889634f
#define LN2    0.6931471805599453f

__device__ __align__(16) float Eexp[(size_t)B * T * EST];   // ~34.6 MB static scratch
__device__ float g_loss[B];
__device__ int   g_ctr = 0;

__device__ __forceinline__ float ex2f(float x) {
    float y; asm("ex2.approx.f32 %0, %1;" : "=f"(y) : "f"(x)); return y;
}
__device__ __forceinline__ float lg2f(float x) {
    float y; asm("lg2.approx.f32 %0, %1;" : "=f"(y) : "f"(x)); return y;
}
__device__ __forceinline__ float lse2log(float a, float b) {   // log2-domain
    const float m  = fmaxf(a, b);
    const float mn = fminf(a, b);
    return m + lg2f(1.0f + ex2f(mn - m));
}

// ---------- Kernel 1: Eexp[b][t][li] = exp(outputs[b,t,lab[li]]); [128] = blank ------
__global__ __launch_bounds__(256)
void emit_exp(const float* __restrict__ outputs, const int* __restrict__ labels) {
    __shared__ int lab[L];
    const int nblk = T / 8;
    const int b   = blockIdx.x / nblk;
    const int t0  = (blockIdx.x % nblk) * 8;
    const int tid = threadIdx.x;

    if (tid < L) lab[tid] = __ldg(labels + b * L + tid);
    __syncthreads();

    const int li   = tid & 127;
    const int half = tid >> 7;
    const int colv = lab[li];

    #pragma unroll
    for (int r2 = 0; r2 < 4; ++r2) {
        const int r = t0 + r2 * 2 + half;
        const float* row  = outputs + ((size_t)b * T + r) * V;
        float*       Erow = Eexp    + ((size_t)b * T + r) * EST;
        Erow[li] = ex2f(__ldg(row + colv) * LOG2E);
        if (li == 0) Erow[128] = ex2f(__ldg(row) * LOG2E);
    }
}

// ---------- Kernel 2: single-warp linear recursion, per-lane exponent tracking -------
__global__ __launch_bounds__(32, 1)
void ctc_rec(const int* __restrict__ labels,
             const int* __restrict__ output_lengths,
             const int* __restrict__ label_lengths,
             float* __restrict__ out) {
    __shared__ float fin[2];
    __shared__ int   finE[2];

    const int b    = blockIdx.x;
    const int lane = threadIdx.x;

    const int olen = output_lengths[b];
    const int llen = label_lengths[b];
    const int tcap = olen - 1;
    const int s0g  = 2 * llen - 1;           // odd
    const int s1g  = 2 * llen;               // even (or 256)

    const int* lb = labels + b * L;
    bool skp[4];
    #pragma unroll
    for (int j = 0; j < 4; ++j) {
        const int li = 4 * lane + j;
        skp[j] = (li > 0) && (__ldg(lb + li) != __ldg(lb + li - 1));
    }

    bool o0[4], o1[4];
    #pragma unroll
    for (int j = 0; j < 4; ++j) {
        o0[j] = (s0g == 8 * lane + 2 * j + 1);
        o1[j] = (s1g == 8 * lane + 2 * j);
    }
    const bool oC   = (lane == 31) && (s1g == 256);
    const bool own0 = o0[0] || o0[1] || o0[2] || o0[3];
    const bool own1 = o1[0] || o1[1] || o1[2] || o1[3] || oC;

    const float* Eb = Eexp + (size_t)b * T * EST;

    // ---- t = 0 ----
    float a0=0,a1=0,a2=0,a3=0,a4=0,a5=0,a6=0,a7=0, C=0;
    int   cum = 0;
    float cap0 = 1.0f, cap1 = 1.0f;
    int   capE0 = 0, capE1 = 0;
    {
        const float ebl = __ldg(Eb + 128);
        const float el0 = __ldg(Eb + 0);
        if (lane == 0) { a0 = ebl; a1 = el0; }
        if (tcap == 0) {
            cap0 = o0[0] ? a1 : cap0;
            cap1 = o1[0] ? a0 : cap1;
        }
    }

    // emit lookahead: slot k holds row tb+k
    float4 el[DP];
    float  eb[DP];
    #pragma unroll
    for (int k = 0; k < DP; ++k) {
        const float* rp = Eb + (size_t)(1 + k) * EST;
        el[k] = __ldg((const float4*)(rp) + lane);
        eb[k] = __ldg(rp + 128);
    }

    // ---- main: 256 blocks of 4 steps (t = 1..1024; step 1024 is harmless overshoot) --
    for (int tb = 1; tb < T; tb += 4) {
        // block top: cross-lane scale difference (static within the block)
        int cumP = __shfl_up_sync(FULLM, cum, 1);
        int db   = cumP - cum;
        if (lane > 0 && db > 40) {     // adopt sender scale (frontier / dominated lane)
            a0=0;a1=0;a2=0;a3=0;a4=0;a5=0;a6=0;a7=0;C=0;
            cum = cumP; db = 0;
        }
        const int dbc = (db < -126) ? -126 : db;   // db <= 40 here
        const float bscale = __uint_as_float((unsigned)(127 + dbc) << 23);

        #pragma unroll
        for (int k = 0; k < 4; ++k) {
            const int t = tb + k;

            float b7 = __shfl_up_sync(FULLM, a7, 1);
            const float b7n = (lane == 0) ? 0.0f : b7 * bscale;

            const float4 e4 = el[k];
            const float  bl = eb[k];

            C  = (C  + a7) * bl;
            a7 = (a7 + a6 + (skp[3] ? a5 : 0.0f)) * e4.w;
            a6 = (a6 + a5) * bl;
            a5 = (a5 + a4 + (skp[2] ? a3 : 0.0f)) * e4.z;
            a4 = (a4 + a3) * bl;
            a3 = (a3 + a2 + (skp[1] ? a1 : 0.0f)) * e4.y;
            a2 = (a2 + a1) * bl;
            a1 = (a1 + a0 + (skp[0] ? b7n : 0.0f)) * e4.x;
            a0 = (a0 + b7n) * bl;

            if (t == tcap) {
                cap0 = o0[0] ? a1 : cap0;  cap0 = o0[1] ? a3 : cap0;
                cap0 = o0[2] ? a5 : cap0;  cap0 = o0[3] ? a7 : cap0;
                cap1 = o1[0] ? a0 : cap1;  cap1 = o1[1] ? a2 : cap1;
                cap1 = o1[2] ? a4 : cap1;  cap1 = o1[3] ? a6 : cap1;
                cap1 = oC    ? C  : cap1;
                capE0 = cum; capE1 = cum;
            }

            // refill slot k with row t+4 (clamped; overshoot rows unused)
            int tr = t + 4; tr = (tr < T) ? tr : (T - 1);
            const float* rp = Eb + (size_t)tr * EST;
            el[k] = __ldg((const float4*)(rp) + lane);
            eb[k] = __ldg(rp + 128);
        }

        // per-lane renorm (exponent-field trick; mx==0 -> boost clamps, values stay 0)
        const float mx = fmaxf(fmaxf(fmaxf(a0, a1), fmaxf(a2, a3)),
                               fmaxf(fmaxf(a4, a5), fmaxf(a6, fmaxf(a7, C))));
        const int ee   = (int)((__float_as_uint(mx) >> 23) & 0xffu);
        int radj = ee - 127;
        radj = (radj < -90) ? -90 : radj;
        radj = (radj > 120) ? 120 : radj;
        const float sf = __uint_as_float((unsigned)(127 - radj) << 23);
        a0*=sf; a1*=sf; a2*=sf; a3*=sf; a4*=sf; a5*=sf; a6*=sf; a7*=sf; C*=sf;
        cum += radj;
    }

    // ---- finish ----
    if (own0) { fin[0] = cap0; finE[0] = capE0; }
    if (own1) { fin[1] = cap1; finE[1] = capE1; }
    __syncwarp();

    if (lane == 0) {
        const float l0 = lg2f(fin[0]) + (float)finE[0];
        const float l1 = lg2f(fin[1]) + (float)finE[1];
        const float ll = lse2log(l0, l1) * LN2;
        g_loss[b] = -ll / (float)llen;
        __threadfence();
        const int old = atomicAdd(&g_ctr, 1);
        if (old == B - 1) {
            __threadfence();
            float s = 0.0f;
            #pragma unroll 8
            for (int i = 0; i < B; ++i) s += g_loss[i];
            *out = s * (1.0f / (float)B);
            g_ctr = 0;   // reset for next graph replay
        }
    }
}

extern "C" void kernel_launch(void* const* d_in, const int* in_sizes, int n_in,
                              void* d_out, int out_size) {
    const float* outputs        = (const float*)d_in[0];
    const int*   labels         = (const int*)d_in[1];
    const int*   output_lengths = (const int*)d_in[2];
    const int*   label_lengths  = (const int*)d_in[3];
    float* out = (float*)d_out;

    emit_exp<<<B * (T / 8), 256>>>(outputs, labels);
    ctc_rec<<<B, 32>>>(labels, output_lengths, label_lengths, out);
}

// round 10
// speedup vs baseline: 3.0235x; 1.3251x over previous
#include <cuda_runtime.h>
#include <cstdint>

constexpr int B = 64;
constexpr int T = 1024;
constexpr int V = 512;
constexpr int L = 128;
constexpr int EST = 132;     // emit row stride (floats): [lab0..lab127, blank, pad3]
constexpr int DP  = 8;       // emit lookahead = renorm block size

#define FULLM  0xffffffffu
#define LOG2E  1.4426950408889634f
#define LN2    0.6931471805599453f

__device__ __align__(16) float Eexp[(size_t)B * T * EST];   // ~34.6 MB static scratch
__device__ float g_loss[B];
__device__ int   g_ctr = 0;

__device__ __forceinline__ float ex2f(float x) {
    float y; asm("ex2.approx.f32 %0, %1;" : "=f"(y) : "f"(x)); return y;
}
__device__ __forceinline__ float lg2f(float x) {
    float y; asm("lg2.approx.f32 %0, %1;" : "=f"(y) : "f"(x)); return y;
}
__device__ __forceinline__ float lse2log(float a, float b) {
    const float m  = fmaxf(a, b);
    const float mn = fminf(a, b);
    return m + lg2f(1.0f + ex2f(mn - m));
}

// ---------- Kernel 1: Eexp[b][t][li] = exp(outputs[b,t,lab[li]]); [128] = blank ------
__global__ __launch_bounds__(256)
void emit_exp(const float* __restrict__ outputs, const int* __restrict__ labels) {
    __shared__ int lab[L];
    const int nblk = T / 8;
    const int b   = blockIdx.x / nblk;
    const int t0  = (blockIdx.x % nblk) * 8;
    const int tid = threadIdx.x;

    if (tid < L) lab[tid] = __ldg(labels + b * L + tid);
    __syncthreads();

    const int li   = tid & 127;
    const int half = tid >> 7;
    const int colv = lab[li];

    #pragma unroll
    for (int r2 = 0; r2 < 4; ++r2) {
        const int r = t0 + r2 * 2 + half;
        const float* row  = outputs + ((size_t)b * T + r) * V;
        float*       Erow = Eexp    + ((size_t)b * T + r) * EST;
        Erow[li] = ex2f(__ldg(row + colv) * LOG2E);
        if (li == 0) Erow[128] = ex2f(__ldg(row) * LOG2E);
    }
}

// ---------- Kernel 2: single-warp linear recursion, per-lane exponent tracking -------
__global__ __launch_bounds__(32, 1)
void ctc_rec(const int* __restrict__ labels,
             const int* __restrict__ output_lengths,
             const int* __restrict__ label_lengths,
             float* __restrict__ out) {
    __shared__ float fin[2];
    __shared__ int   finE[2];

    const int b    = blockIdx.x;
    const int lane = threadIdx.x;

    const int olen = output_lengths[b];
    const int llen = label_lengths[b];
    const int tcap = olen - 1;
    const int s0g  = 2 * llen - 1;           // odd
    const int s1g  = 2 * llen;               // even (or 256)

    const int* lb = labels + b * L;
    bool skp0, skp1, skp2, skp3;
    {
        const int li0 = 4 * lane;
        const int c0 = __ldg(lb + li0), c1 = __ldg(lb + li0 + 1);
        const int c2 = __ldg(lb + li0 + 2), c3 = __ldg(lb + li0 + 3);
        skp0 = (li0 > 0) && (c0 != __ldg(lb + li0 - 1));
        skp1 = (c1 != c0); skp2 = (c2 != c1); skp3 = (c3 != c2);
    }

    const bool o0_0 = (s0g == 8 * lane + 1), o0_1 = (s0g == 8 * lane + 3);
    const bool o0_2 = (s0g == 8 * lane + 5), o0_3 = (s0g == 8 * lane + 7);
    const bool o1_0 = (s1g == 8 * lane),     o1_1 = (s1g == 8 * lane + 2);
    const bool o1_2 = (s1g == 8 * lane + 4), o1_3 = (s1g == 8 * lane + 6);
    const bool oC   = (lane == 31) && (s1g == 256);
    const bool own0 = o0_0 || o0_1 || o0_2 || o0_3;
    const bool own1 = o1_0 || o1_1 || o1_2 || o1_3 || oC;

    const float* Eb = Eexp + (size_t)b * T * EST;

    // ---- t = 0 ----
    float a0=0,a1=0,a2=0,a3=0,a4=0,a5=0,a6=0,a7=0, C=0;
    int   cum = 0;
    float cap0 = 1.0f, cap1 = 1.0f;
    int   capE0 = 0, capE1 = 0;
    {
        const float ebl = __ldg(Eb + 128);
        const float el0 = __ldg(Eb + 0);
        if (lane == 0) { a0 = ebl; a1 = el0; }
        if (tcap == 0) {
            cap0 = o0_0 ? a1 : cap0;
            cap1 = o1_0 ? a0 : cap1;
        }
    }

    // emit lookahead: slot k holds row tb+k; initial rows 1..8
    float4 el[DP];
    float  eb[DP];
    #pragma unroll
    for (int k = 0; k < DP; ++k) {
        const float* rp = Eb + (size_t)(1 + k) * EST;
        el[k] = __ldg((const float4*)(rp) + lane);
        eb[k] = __ldg(rp + 128);
    }

    // ---- main: 128 blocks of 8 steps (t = 1..1024; t=1024 is harmless overshoot) ----
    for (int tb = 1; tb < T; tb += 8) {
        // block top: branchless cross-lane scale alignment
        const int  cumP  = __shfl_up_sync(FULLM, cum, 1);
        int        db    = cumP - cum;
        const bool adopt = (lane > 0) && (db > 40);
        a0 = adopt ? 0.0f : a0;  a1 = adopt ? 0.0f : a1;
        a2 = adopt ? 0.0f : a2;  a3 = adopt ? 0.0f : a3;
        a4 = adopt ? 0.0f : a4;  a5 = adopt ? 0.0f : a5;
        a6 = adopt ? 0.0f : a6;  a7 = adopt ? 0.0f : a7;
        C  = adopt ? 0.0f : C;
        cum = adopt ? cumP : cum;
        db  = adopt ? 0 : db;
        db  = (db < -126) ? -126 : db;          // db <= 40 here
        const float bscale = __uint_as_float((unsigned)(127 + db) << 23);

        #pragma unroll
        for (int k = 0; k < 8; ++k) {
            const int t = tb + k;

            const float b7  = __shfl_up_sync(FULLM, a7, 1);
            const float b7n = (lane == 0) ? 0.0f : b7 * bscale;

            const float4 e4 = el[k];
            const float  bl = eb[k];

            C  = (C  + a7) * bl;
            a7 = (a7 + a6 + (skp3 ? a5 : 0.0f)) * e4.w;
            a6 = (a6 + a5) * bl;
            a5 = (a5 + a4 + (skp2 ? a3 : 0.0f)) * e4.z;
            a4 = (a4 + a3) * bl;
            a3 = (a3 + a2 + (skp1 ? a1 : 0.0f)) * e4.y;
            a2 = (a2 + a1) * bl;
            a1 = (a1 + a0 + (skp0 ? b7n : 0.0f)) * e4.x;
            a0 = (a0 + b7n) * bl;

            // branchless capture
            const bool pc  = (t == tcap);
            const bool h0  = pc && own0;
            const bool h1  = pc && own1;
            const float v0 = o0_0 ? a1 : (o0_1 ? a3 : (o0_2 ? a5 : a7));
            const float v1 = o1_0 ? a0 : (o1_1 ? a2 : (o1_2 ? a4 : (oC ? C : a6)));
            cap0  = h0 ? v0  : cap0;
            cap1  = h1 ? v1  : cap1;
            capE0 = h0 ? cum : capE0;
            capE1 = h1 ? cum : capE1;

            // refill slot k with row t+8 (clamped; overshoot rows unused)
            int tr = t + 8; tr = (tr < T) ? tr : (T - 1);
            const float* rp = Eb + (size_t)tr * EST;
            el[k] = __ldg((const float4*)(rp) + lane);
            eb[k] = __ldg(rp + 128);
        }

        // per-lane renorm (exponent-field trick; all-zero lane clamps at -90)
        const float mx = fmaxf(fmaxf(fmaxf(a0, a1), fmaxf(a2, a3)),
                               fmaxf(fmaxf(a4, a5), fmaxf(a6, fmaxf(a7, C))));
        const int ee   = (int)((__float_as_uint(mx) >> 23) & 0xffu);
        int radj = ee - 127;
        radj = (radj < -90) ? -90 : radj;
        radj = (radj > 120) ? 120 : radj;
        const float sf = __uint_as_float((unsigned)(127 - radj) << 23);
        a0*=sf; a1*=sf; a2*=sf; a3*=sf; a4*=sf; a5*=sf; a6*=sf; a7*=sf; C*=sf;
        cum += radj;
    }

    // ---- finish ----
    if (own0) { fin[0] = cap0; finE[0] = capE0; }
    if (own1) { fin[1] = cap1; finE[1] = capE1; }
    __syncwarp();

    if (lane == 0) {
        const float l0 = lg2f(fin[0]) + (float)finE[0];
        const float l1 = lg2f(fin[1]) + (float)finE[1];
        const float ll = lse2log(l0, l1) * LN2;
        g_loss[b] = -ll / (float)llen;
        __threadfence();
        const int old = atomicAdd(&g_ctr, 1);
        if (old == B - 1) {
            __threadfence();
            float s = 0.0f;
            #pragma unroll 8
            for (int i = 0; i < B; ++i) s += g_loss[i];
            *out = s * (1.0f / (float)B);
            g_ctr = 0;   // reset for next graph replay
        }
    }
}

extern "C" void kernel_launch(void* const* d_in, const int* in_sizes, int n_in,
                              void* d_out, int out_size) {
    const float* outputs        = (const float*)d_in[0];
    const int*   labels         = (const int*)d_in[1];
    const int*   output_lengths = (const int*)d_in[2];
    const int*   label_lengths  = (const int*)d_in[3];
    float* out = (float*)d_out;

    emit_exp<<<B * (T / 8), 256>>>(outputs, labels);
    ctc_rec<<<B, 32>>>(labels, output_lengths, label_lengths, out);
}

// round 11
// speedup vs baseline: 3.5335x; 1.1687x over previous
#include <cuda_runtime.h>
#include <cstdint>

constexpr int B = 64;
constexpr int T = 1024;
constexpr int V = 512;
constexpr int L = 128;
constexpr int EST  = 132;    // emit row stride (floats): [lab0..lab127, blank, pad3]
constexpr int TPAD = T + 16; // padded rows; overshoot rows stay zero (harmless)
constexpr int DP   = 8;      // emit lookahead = renorm block size

#define FULLM  0xffffffffu
#define LOG2E  1.4426950408889634f
#define LN2    0.6931471805599453f

__device__ __align__(16) float Eexp[(size_t)B * TPAD * EST];   // ~35.1 MB, zero-init
__device__ float g_loss[B];
__device__ int   g_ctr = 0;

__device__ __forceinline__ float ex2f(float x) {
    float y; asm("ex2.approx.f32 %0, %1;" : "=f"(y) : "f"(x)); return y;
}
__device__ __forceinline__ float lg2f(float x) {
    float y; asm("lg2.approx.f32 %0, %1;" : "=f"(y) : "f"(x)); return y;
}
__device__ __forceinline__ float lse2log(float a, float b) {
    const float m  = fmaxf(a, b);
    const float mn = fminf(a, b);
    return m + lg2f(1.0f + ex2f(mn - m));
}

// ---------- Kernel 1: Eexp[b][t][li] = exp(outputs[b,t,lab[li]]); [128] = blank ------
__global__ __launch_bounds__(256)
void emit_exp(const float* __restrict__ outputs, const int* __restrict__ labels) {
    __shared__ int lab[L];
    const int nblk = T / 8;
    const int b   = blockIdx.x / nblk;
    const int t0  = (blockIdx.x % nblk) * 8;
    const int tid = threadIdx.x;

    if (tid < L) lab[tid] = __ldg(labels + b * L + tid);
    __syncthreads();

    const int li   = tid & 127;
    const int half = tid >> 7;
    const int colv = lab[li];

    #pragma unroll
    for (int r2 = 0; r2 < 4; ++r2) {
        const int r = t0 + r2 * 2 + half;
        const float* row  = outputs + ((size_t)b * T + r) * V;
        float*       Erow = Eexp    + ((size_t)b * TPAD + r) * EST;
        Erow[li] = ex2f(__ldg(row + colv) * LOG2E);
        if (li == 0) Erow[128] = ex2f(__ldg(row) * LOG2E);
    }
}

// ---------- Kernel 2: single-warp linear recursion, per-lane exponent tracking -------
__global__ __launch_bounds__(32, 1)
void ctc_rec(const int* __restrict__ labels,
             const int* __restrict__ output_lengths,
             const int* __restrict__ label_lengths,
             float* __restrict__ out) {
    __shared__ float fin[2];
    __shared__ int   finE[2];

    const int b    = blockIdx.x;
    const int lane = threadIdx.x;

    const int olen = output_lengths[b];
    const int llen = label_lengths[b];
    const int tcap = olen - 1;
    const int s0g  = 2 * llen - 1;           // odd
    const int s1g  = 2 * llen;               // even (or 256)

    const int* lb = labels + b * L;
    float s0, s1, s2, s3;                    // skip weights as 0/1 floats
    {
        const int li0 = 4 * lane;
        const int c0 = __ldg(lb + li0), c1 = __ldg(lb + li0 + 1);
        const int c2 = __ldg(lb + li0 + 2), c3 = __ldg(lb + li0 + 3);
        s0 = ((li0 > 0) && (c0 != __ldg(lb + li0 - 1))) ? 1.0f : 0.0f;
        s1 = (c1 != c0) ? 1.0f : 0.0f;
        s2 = (c2 != c1) ? 1.0f : 0.0f;
        s3 = (c3 != c2) ? 1.0f : 0.0f;
    }

    const bool o0_0 = (s0g == 8 * lane + 1), o0_1 = (s0g == 8 * lane + 3);
    const bool o0_2 = (s0g == 8 * lane + 5), o0_3 = (s0g == 8 * lane + 7);
    const bool o1_0 = (s1g == 8 * lane),     o1_1 = (s1g == 8 * lane + 2);
    const bool o1_2 = (s1g == 8 * lane + 4), o1_3 = (s1g == 8 * lane + 6);
    const bool oC   = (lane == 31) && (s1g == 256);
    const bool own0 = o0_0 || o0_1 || o0_2 || o0_3;
    const bool own1 = o1_0 || o1_1 || o1_2 || o1_3 || oC;

    const float* Eb = Eexp + (size_t)b * TPAD * EST;

    // ---- t = 0 ----
    float a0=0,a1=0,a2=0,a3=0,a4=0,a5=0,a6=0,a7=0, C=0;
    int   cum = 0;
    float cap0 = 1.0f, cap1 = 1.0f;
    int   capE0 = 0, capE1 = 0;
    {
        const float ebl = __ldg(Eb + 128);
        const float el0 = __ldg(Eb + 0);
        if (lane == 0) { a0 = ebl; a1 = el0; }
        if (tcap == 0) {
            cap0 = o0_0 ? a1 : cap0;
            cap1 = o1_0 ? a0 : cap1;
        }
    }

    // emit lookahead: slot k holds row tb+k; initial rows 1..8
    float4 el[DP];
    float  eb[DP];
    #pragma unroll
    for (int k = 0; k < DP; ++k) {
        const float* rp = Eb + (size_t)(1 + k) * EST;
        el[k] = __ldg((const float4*)(rp) + lane);
        eb[k] = __ldg(rp + 128);
    }

    // one recursion step; CAPF selects capture code at compile time
    #define CTC_STEP(K_, TB_, BS0_, CAPF_)                                        \
    {                                                                             \
        const float b7  = __shfl_up_sync(FULLM, a7, 1);                           \
        const float b7n = b7 * (BS0_);                                            \
        const float4 e4 = el[K_];                                                 \
        const float  bl = eb[K_];                                                 \
        C  = (C  + a7) * bl;                                                      \
        a7 = (a7 + fmaf(s3, a5, a6 )) * e4.w;                                     \
        a6 = (a6 + a5) * bl;                                                      \
        a5 = (a5 + fmaf(s2, a3, a4 )) * e4.z;                                     \
        a4 = (a4 + a3) * bl;                                                      \
        a3 = (a3 + fmaf(s1, a1, a2 )) * e4.y;                                     \
        a2 = (a2 + a1) * bl;                                                      \
        a1 = (a1 + fmaf(s0, b7n, a0)) * e4.x;                                     \
        a0 = (a0 + b7n) * bl;                                                     \
        if (CAPF_) {                                                              \
            const bool pc  = ((TB_) + (K_) == tcap);                              \
            const bool h0  = pc && own0;                                          \
            const bool h1  = pc && own1;                                          \
            const float v0 = o0_0 ? a1 : (o0_1 ? a3 : (o0_2 ? a5 : a7));          \
            const float v1 = o1_0 ? a0 : (o1_1 ? a2 :                             \
                             (o1_2 ? a4 : (oC ? C : a6)));                        \
            cap0  = h0 ? v0  : cap0;  cap1  = h1 ? v1  : cap1;                    \
            capE0 = h0 ? cum : capE0; capE1 = h1 ? cum : capE1;                   \
        }                                                                         \
        const float* rp_ = rblk + (K_) * EST;                                     \
        el[K_] = __ldg((const float4*)(rp_) + lane);                              \
        eb[K_] = __ldg(rp_ + 128);                                                \
    }

    // ---- main: 128 blocks of 8 steps (t = 1..1024; t=1024 is harmless overshoot) ----
    for (int tb = 1; tb < T; tb += 8) {
        // block top: branchless cross-lane scale alignment
        const int  cumP  = __shfl_up_sync(FULLM, cum, 1);
        int        db    = cumP - cum;
        const bool adopt = (lane > 0) && (db > 40);
        a0 = adopt ? 0.0f : a0;  a1 = adopt ? 0.0f : a1;
        a2 = adopt ? 0.0f : a2;  a3 = adopt ? 0.0f : a3;
        a4 = adopt ? 0.0f : a4;  a5 = adopt ? 0.0f : a5;
        a6 = adopt ? 0.0f : a6;  a7 = adopt ? 0.0f : a7;
        C  = adopt ? 0.0f : C;
        cum = adopt ? cumP : cum;
        db  = adopt ? 0 : db;
        db  = (db < -126) ? -126 : db;          // db <= 40 here
        const float bscale = __uint_as_float((unsigned)(127 + db) << 23);
        const float bs0    = (lane == 0) ? 0.0f : bscale;

        const float* rblk = Eb + (size_t)(tb + 8) * EST;   // refill rows tb+8..tb+15

        if ((unsigned)(tcap - tb) < 8u) {       // capture block (runs at most twice)
            #pragma unroll
            for (int k = 0; k < 8; ++k) CTC_STEP(k, tb, bs0, true)
        } else {                                 // hot block, no capture code
            #pragma unroll
            for (int k = 0; k < 8; ++k) CTC_STEP(k, tb, bs0, false)
        }

        // per-lane renorm (exponent-field trick; all-zero lane clamps at -90)
        const float mx = fmaxf(fmaxf(fmaxf(a0, a1), fmaxf(a2, a3)),
                               fmaxf(fmaxf(a4, a5), fmaxf(a6, fmaxf(a7, C))));
        const int ee   = (int)((__float_as_uint(mx) >> 23) & 0xffu);
        int radj = ee - 127;
        radj = (radj < -90) ? -90 : radj;
        radj = (radj > 120) ? 120 : radj;
        const float sf = __uint_as_float((unsigned)(127 - radj) << 23);
        a0*=sf; a1*=sf; a2*=sf; a3*=sf; a4*=sf; a5*=sf; a6*=sf; a7*=sf; C*=sf;
        cum += radj;
    }
    #undef CTC_STEP

    // ---- finish ----
    if (own0) { fin[0] = cap0; finE[0] = capE0; }
    if (own1) { fin[1] = cap1; finE[1] = capE1; }
    __syncwarp();

    if (lane == 0) {
        const float l0 = lg2f(fin[0]) + (float)finE[0];
        const float l1 = lg2f(fin[1]) + (float)finE[1];
        const float ll = lse2log(l0, l1) * LN2;
        g_loss[b] = -ll / (float)llen;
        __threadfence();
        const int old = atomicAdd(&g_ctr, 1);
        if (old == B - 1) {
            __threadfence();
            float s = 0.0f;
            #pragma unroll 8
            for (int i = 0; i < B; ++i) s += g_loss[i];
            *out = s * (1.0f / (float)B);
            g_ctr = 0;   // reset for next graph replay
        }
    }
}

extern "C" void kernel_launch(void* const* d_in, const int* in_sizes, int n_in,
                              void* d_out, int out_size) {
    const float* outputs        = (const float*)d_in[0];
    const int*   labels         = (const int*)d_in[1];
    const int*   output_lengths = (const int*)d_in[2];
    const int*   label_lengths  = (const int*)d_in[3];
    float* out = (float*)d_out;

    emit_exp<<<B * (T / 8), 256>>>(outputs, labels);
    ctc_rec<<<B, 32>>>(labels, output_lengths, label_lengths, out);
}

// round 12
// speedup vs baseline: 4.6512x; 1.3163x over previous
#include <cuda_runtime.h>
#include <cstdint>

constexpr int B = 64;
constexpr int T = 1024;
constexpr int V = 512;
constexpr int L = 128;
constexpr int EST  = 132;    // emit row stride (floats): [lab0..lab127, blank, pad3]
constexpr int TPAD = T + 16; // padded rows; overshoot rows stay zero (harmless)

#define FULLM  0xffffffffu
#define LOG2E  1.4426950408889634f
#define LN2    0.6931471805599453f

__device__ __align__(16) float Eexp[(size_t)B * TPAD * EST];   // ~35.1 MB, zero-init
__device__ float g_loss[B];
__device__ int   g_ctr = 0;

__device__ __forceinline__ float ex2f(float x) {
    float y; asm("ex2.approx.f32 %0, %1;" : "=f"(y) : "f"(x)); return y;
}
__device__ __forceinline__ float lg2f(float x) {
    float y; asm("lg2.approx.f32 %0, %1;" : "=f"(y) : "f"(x)); return y;
}
__device__ __forceinline__ float lse2log(float a, float b) {
    const float m  = fmaxf(a, b);
    const float mn = fminf(a, b);
    return m + lg2f(1.0f + ex2f(mn - m));
}

// ---------- Kernel 1: Eexp[b][t][li] = exp(outputs[b,t,lab[li]]); [128] = blank ------
__global__ __launch_bounds__(256)
void emit_exp(const float* __restrict__ outputs, const int* __restrict__ labels) {
    __shared__ int lab[L];
    const int nblk = T / 8;
    const int b   = blockIdx.x / nblk;
    const int t0  = (blockIdx.x % nblk) * 8;
    const int tid = threadIdx.x;

    if (tid < L) lab[tid] = __ldg(labels + b * L + tid);
    __syncthreads();

    const int li   = tid & 127;
    const int half = tid >> 7;
    const int colv = lab[li];

    #pragma unroll
    for (int r2 = 0; r2 < 4; ++r2) {
        const int r = t0 + r2 * 2 + half;
        const float* row  = outputs + ((size_t)b * T + r) * V;
        float*       Erow = Eexp    + ((size_t)b * TPAD + r) * EST;
        Erow[li] = ex2f(__ldg(row + colv) * LOG2E);
        if (li == 0) Erow[128] = ex2f(__ldg(row) * LOG2E);
    }
}

// ---------- Kernel 2: single-warp linear recursion, per-lane exponent tracking -------
__global__ __launch_bounds__(32, 1)
void ctc_rec(const int* __restrict__ labels,
             const int* __restrict__ output_lengths,
             const int* __restrict__ label_lengths,
             float* __restrict__ out) {
    __shared__ float fin[2];
    __shared__ int   finE[2];

    const int b    = blockIdx.x;
    const int lane = threadIdx.x;

    const int olen = output_lengths[b];
    const int llen = label_lengths[b];
    const int tcap = olen - 1;
    const int s0g  = 2 * llen - 1;           // odd
    const int s1g  = 2 * llen;               // even (or 256)

    const int* lb = labels + b * L;
    float s0, s1, s2, s3;                    // skip weights as 0/1 floats
    {
        const int li0 = 4 * lane;
        const int c0 = __ldg(lb + li0), c1 = __ldg(lb + li0 + 1);
        const int c2 = __ldg(lb + li0 + 2), c3 = __ldg(lb + li0 + 3);
        s0 = ((li0 > 0) && (c0 != __ldg(lb + li0 - 1))) ? 1.0f : 0.0f;
        s1 = (c1 != c0) ? 1.0f : 0.0f;
        s2 = (c2 != c1) ? 1.0f : 0.0f;
        s3 = (c3 != c2) ? 1.0f : 0.0f;
    }

    const bool o0_0 = (s0g == 8 * lane + 1), o0_1 = (s0g == 8 * lane + 3);
    const bool o0_2 = (s0g == 8 * lane + 5), o0_3 = (s0g == 8 * lane + 7);
    const bool o1_0 = (s1g == 8 * lane),     o1_1 = (s1g == 8 * lane + 2);
    const bool o1_2 = (s1g == 8 * lane + 4), o1_3 = (s1g == 8 * lane + 6);
    const bool oC   = (lane == 31) && (s1g == 256);
    const bool own0 = o0_0 || o0_1 || o0_2 || o0_3;
    const bool own1 = o1_0 || o1_1 || o1_2 || o1_3 || oC;

    const float* Eb = Eexp + (size_t)b * TPAD * EST;

    // ---- t = 0 ----
    float a0=0,a1=0,a2=0,a3=0,a4=0,a5=0,a6=0,a7=0, C=0;
    int   cum = 0;
    float cap0 = 1.0f, cap1 = 1.0f;
    int   capE0 = 0, capE1 = 0;
    {
        const float ebl = __ldg(Eb + 128);
        const float el0 = __ldg(Eb + 0);
        if (lane == 0) { a0 = ebl; a1 = el0; }
        if (tcap == 0) {
            cap0 = o0_0 ? a1 : cap0;
            cap1 = o1_0 ? a0 : cap1;
        }
    }

    // double-buffered emit registers; buffer holds one 8-row block
    float4 elA[8], elB[8];
    float  ebA[8], ebB[8];
    #pragma unroll
    for (int k = 0; k < 8; ++k) {       // preload block tb=1 (rows 1..8) into A
        const float* rp = Eb + (size_t)(1 + k) * EST;
        elA[k] = __ldg((const float4*)(rp) + lane);
        ebA[k] = __ldg(rp + 128);
    }

    // one recursion step consuming buffer ELC/EBC slot K_
    #define CTC_STEP(K_, TB_, BS0_, ELC, EBC, CAPF_)                              \
    {                                                                             \
        const float b7  = __shfl_up_sync(FULLM, a7, 1);                           \
        const float b7n = b7 * (BS0_);                                            \
        const float4 e4 = ELC[K_];                                                \
        const float  bl = EBC[K_];                                                \
        C  = (C  + a7) * bl;                                                      \
        a7 = (a7 + fmaf(s3, a5, a6 )) * e4.w;                                     \
        a6 = (a6 + a5) * bl;                                                      \
        a5 = (a5 + fmaf(s2, a3, a4 )) * e4.z;                                     \
        a4 = (a4 + a3) * bl;                                                      \
        a3 = (a3 + fmaf(s1, a1, a2 )) * e4.y;                                     \
        a2 = (a2 + a1) * bl;                                                      \
        a1 = (a1 + fmaf(s0, b7n, a0)) * e4.x;                                     \
        a0 = (a0 + b7n) * bl;                                                     \
        if (CAPF_) {                                                              \
            const bool pc  = ((TB_) + (K_) == tcap);                              \
            const bool h0  = pc && own0;                                          \
            const bool h1  = pc && own1;                                          \
            const float v0 = o0_0 ? a1 : (o0_1 ? a3 : (o0_2 ? a5 : a7));          \
            const float v1 = o1_0 ? a0 : (o1_1 ? a2 :                             \
                             (o1_2 ? a4 : (oC ? C : a6)));                        \
            cap0  = h0 ? v0  : cap0;  cap1  = h1 ? v1  : cap1;                    \
            capE0 = h0 ? cum : capE0; capE1 = h1 ? cum : capE1;                   \
        }                                                                         \
    }

    // one 8-step block: consumes ELC/EBC, loads the NEXT block into ELN/EBN
    #define CTC_BLOCK(TB_, ELC, EBC, ELN, EBN)                                    \
    {                                                                             \
        const int  cumP  = __shfl_up_sync(FULLM, cum, 1);                         \
        int        db    = cumP - cum;                                            \
        const bool adopt = (lane > 0) && (db > 40);                               \
        a0 = adopt ? 0.0f : a0;  a1 = adopt ? 0.0f : a1;                          \
        a2 = adopt ? 0.0f : a2;  a3 = adopt ? 0.0f : a3;                          \
        a4 = adopt ? 0.0f : a4;  a5 = adopt ? 0.0f : a5;                          \
        a6 = adopt ? 0.0f : a6;  a7 = adopt ? 0.0f : a7;                          \
        C  = adopt ? 0.0f : C;                                                    \
        cum = adopt ? cumP : cum;                                                 \
        db  = adopt ? 0 : db;                                                     \
        db  = (db < -126) ? -126 : db;                                            \
        const float bscale = __uint_as_float((unsigned)(127 + db) << 23);         \
        const float bs0    = (lane == 0) ? 0.0f : bscale;                         \
        const float* rblk  = Eb + (size_t)((TB_) + 8) * EST;                      \
        _Pragma("unroll")                                                         \
        for (int k_ = 0; k_ < 8; ++k_) {                                          \
            ELN[k_] = __ldg((const float4*)(rblk + k_ * EST) + lane);             \
            EBN[k_] = __ldg(rblk + k_ * EST + 128);                               \
        }                                                                         \
        if ((unsigned)(tcap - (TB_)) < 8u) {                                      \
            _Pragma("unroll")                                                     \
            for (int k_ = 0; k_ < 8; ++k_)                                        \
                CTC_STEP(k_, TB_, bs0, ELC, EBC, true)                            \
        } else {                                                                  \
            _Pragma("unroll")                                                     \
            for (int k_ = 0; k_ < 8; ++k_)                                        \
                CTC_STEP(k_, TB_, bs0, ELC, EBC, false)                           \
        }                                                                         \
        const float mx = fmaxf(fmaxf(fmaxf(a0, a1), fmaxf(a2, a3)),               \
                               fmaxf(fmaxf(a4, a5), fmaxf(a6, fmaxf(a7, C))));    \
        const int ee   = (int)((__float_as_uint(mx) >> 23) & 0xffu);              \
        int radj = ee - 127;                                                      \
        radj = (radj < -90) ? -90 : radj;                                         \
        radj = (radj > 120) ? 120 : radj;                                         \
        const float sf = __uint_as_float((unsigned)(127 - radj) << 23);           \
        a0*=sf; a1*=sf; a2*=sf; a3*=sf; a4*=sf; a5*=sf; a6*=sf; a7*=sf; C*=sf;    \
        cum += radj;                                                              \
    }

    // ---- main: 64 block-pairs (t = 1..1024; t=1024 is harmless overshoot) ----
    for (int tb = 1; tb < T; tb += 16) {
        CTC_BLOCK(tb,     elA, ebA, elB, ebB)
        CTC_BLOCK(tb + 8, elB, ebB, elA, ebA)
    }
    #undef CTC_STEP
    #undef CTC_BLOCK

    // ---- finish ----
    if (own0) { fin[0] = cap0; finE[0] = capE0; }
    if (own1) { fin[1] = cap1; finE[1] = capE1; }
    __syncwarp();

    if (lane == 0) {
        const float l0 = lg2f(fin[0]) + (float)finE[0];
        const float l1 = lg2f(fin[1]) + (float)finE[1];
        const float ll = lse2log(l0, l1) * LN2;
        g_loss[b] = -ll / (float)llen;
        __threadfence();
        const int old = atomicAdd(&g_ctr, 1);
        if (old == B - 1) {
            __threadfence();
            float s = 0.0f;
            #pragma unroll 8
            for (int i = 0; i < B; ++i) s += g_loss[i];
            *out = s * (1.0f / (float)B);
            g_ctr = 0;   // reset for next graph replay
        }
    }
}

extern "C" void kernel_launch(void* const* d_in, const int* in_sizes, int n_in,
                              void* d_out, int out_size) {
    const float* outputs        = (const float*)d_in[0];
    const int*   labels         = (const int*)d_in[1];
    const int*   output_lengths = (const int*)d_in[2];
    const int*   label_lengths  = (const int*)d_in[3];
    float* out = (float*)d_out;

    emit_exp<<<B * (T / 8), 256>>>(outputs, labels);
    ctc_rec<<<B, 32>>>(labels, output_lengths, label_lengths, out);
}

// round 13
// speedup vs baseline: 5.2611x; 1.1311x over previous
#include <cuda_runtime.h>
#include <cstdint>

constexpr int B = 64;
constexpr int T = 1024;
constexpr int V = 512;
constexpr int L = 128;
constexpr int EST  = 132;    // emit row stride (floats): [lab0..lab127, blank, pad3]
constexpr int TPAD = T + 32; // padded rows; overshoot rows stay zero (harmless)

#define FULLM  0xffffffffu
#define LOG2E  1.4426950408889634f
#define LN2    0.6931471805599453f

__device__ __align__(16) float Eexp[(size_t)B * TPAD * EST];   // ~35.6 MB, zero-init
__device__ float g_loss[B];
__device__ int   g_ctr = 0;

__device__ __forceinline__ float ex2f(float x) {
    float y; asm("ex2.approx.f32 %0, %1;" : "=f"(y) : "f"(x)); return y;
}
__device__ __forceinline__ float lg2f(float x) {
    float y; asm("lg2.approx.f32 %0, %1;" : "=f"(y) : "f"(x)); return y;
}
__device__ __forceinline__ float lse2log(float a, float b) {
    const float m  = fmaxf(a, b);
    const float mn = fminf(a, b);
    return m + lg2f(1.0f + ex2f(mn - m));
}

// ---------- Kernel 1: Eexp[b][t][li] = exp(outputs[b,t,lab[li]]); [128] = blank ------
__global__ __launch_bounds__(256)
void emit_exp(const float* __restrict__ outputs, const int* __restrict__ labels) {
    __shared__ int lab[L];
    const int nblk = T / 8;
    const int b   = blockIdx.x / nblk;
    const int t0  = (blockIdx.x % nblk) * 8;
    const int tid = threadIdx.x;

    if (tid < L) lab[tid] = __ldg(labels + b * L + tid);
    __syncthreads();

    const int li   = tid & 127;
    const int half = tid >> 7;
    const int colv = lab[li];

    #pragma unroll
    for (int r2 = 0; r2 < 4; ++r2) {
        const int r = t0 + r2 * 2 + half;
        const float* row  = outputs + ((size_t)b * T + r) * V;
        float*       Erow = Eexp    + ((size_t)b * TPAD + r) * EST;
        Erow[li] = ex2f(__ldg(row + colv) * LOG2E);
        if (li == 0) Erow[128] = ex2f(__ldg(row) * LOG2E);
    }
}

// ---------- Kernel 2: single-warp linear recursion, per-lane exponent tracking -------
__global__ __launch_bounds__(32, 1)
void ctc_rec(const int* __restrict__ labels,
             const int* __restrict__ output_lengths,
             const int* __restrict__ label_lengths,
             float* __restrict__ out) {
    __shared__ float fin[2];
    __shared__ int   finE[2];

    const int b    = blockIdx.x;
    const int lane = threadIdx.x;

    const int olen = output_lengths[b];
    const int llen = label_lengths[b];
    const int tcap = olen - 1;
    const int s0g  = 2 * llen - 1;           // odd
    const int s1g  = 2 * llen;               // even (or 256)

    const int* lb = labels + b * L;
    float s0, s1, s2, s3;                    // skip weights as 0/1 floats
    {
        const int li0 = 4 * lane;
        const int c0 = __ldg(lb + li0), c1 = __ldg(lb + li0 + 1);
        const int c2 = __ldg(lb + li0 + 2), c3 = __ldg(lb + li0 + 3);
        s0 = ((li0 > 0) && (c0 != __ldg(lb + li0 - 1))) ? 1.0f : 0.0f;
        s1 = (c1 != c0) ? 1.0f : 0.0f;
        s2 = (c2 != c1) ? 1.0f : 0.0f;
        s3 = (c3 != c2) ? 1.0f : 0.0f;
    }

    const bool o0_0 = (s0g == 8 * lane + 1), o0_1 = (s0g == 8 * lane + 3);
    const bool o0_2 = (s0g == 8 * lane + 5), o0_3 = (s0g == 8 * lane + 7);
    const bool o1_0 = (s1g == 8 * lane),     o1_1 = (s1g == 8 * lane + 2);
    const bool o1_2 = (s1g == 8 * lane + 4), o1_3 = (s1g == 8 * lane + 6);
    const bool oC   = (lane == 31) && (s1g == 256);
    const bool own0 = o0_0 || o0_1 || o0_2 || o0_3;
    const bool own1 = o1_0 || o1_1 || o1_2 || o1_3 || oC;

    const float* Eb = Eexp + (size_t)b * TPAD * EST;

    // ---- t = 0 ----
    float a0=0,a1=0,a2=0,a3=0,a4=0,a5=0,a6=0,a7=0, C=0;
    int   cum = 0;
    float cap0 = 1.0f, cap1 = 1.0f;
    int   capE0 = 0, capE1 = 0;
    {
        const float ebl = __ldg(Eb + 128);
        const float el0 = __ldg(Eb + 0);
        if (lane == 0) { a0 = ebl; a1 = el0; }
        if (tcap == 0) {
            cap0 = o0_0 ? a1 : cap0;
            cap1 = o1_0 ? a0 : cap1;
        }
    }

    // triple-buffered emit registers; each buffer holds one 8-row block
    float4 elA[8], elB[8], elC[8];
    float  ebA[8], ebB[8], ebC[8];
    #pragma unroll
    for (int k = 0; k < 8; ++k) {       // preload block 0 (rows 1..8) into A
        const float* rp = Eb + (size_t)(1 + k) * EST;
        elA[k] = __ldg((const float4*)(rp) + lane);
        ebA[k] = __ldg(rp + 128);
    }
    #pragma unroll
    for (int k = 0; k < 8; ++k) {       // preload block 1 (rows 9..16) into B
        const float* rp = Eb + (size_t)(9 + k) * EST;
        elB[k] = __ldg((const float4*)(rp) + lane);
        ebB[k] = __ldg(rp + 128);
    }

    float b7pipe = 0.0f;                 // pipelined boundary shfl value

    // one recursion step consuming buffer ELC/EBC slot K_
    #define CTC_STEP(K_, TB_, BS0_, ELC, EBC, CAPF_)                              \
    {                                                                             \
        const float b7n = b7pipe * (BS0_);    /* shfl issued last step */         \
        const float4 e4 = ELC[K_];                                                \
        const float  bl = EBC[K_];                                                \
        C  = (C  + a7) * bl;                                                      \
        const float a7n = (a7 + fmaf(s3, a5, a6)) * e4.w;                         \
        b7pipe = __shfl_up_sync(FULLM, a7n, 1);   /* for next step */             \
        a6 = (a6 + a5) * bl;                                                      \
        a5 = (a5 + fmaf(s2, a3, a4 )) * e4.z;                                     \
        a4 = (a4 + a3) * bl;                                                      \
        a3 = (a3 + fmaf(s1, a1, a2 )) * e4.y;                                     \
        a2 = (a2 + a1) * bl;                                                      \
        a1 = (a1 + fmaf(s0, b7n, a0)) * e4.x;                                     \
        a0 = (a0 + b7n) * bl;                                                     \
        a7 = a7n;                                                                 \
        if (CAPF_) {                                                              \
            const bool pc  = ((TB_) + (K_) == tcap);                              \
            const bool h0  = pc && own0;                                          \
            const bool h1  = pc && own1;                                          \
            const float v0 = o0_0 ? a1 : (o0_1 ? a3 : (o0_2 ? a5 : a7));          \
            const float v1 = o1_0 ? a0 : (o1_1 ? a2 :                             \
                             (o1_2 ? a4 : (oC ? C : a6)));                        \
            cap0  = h0 ? v0  : cap0;  cap1  = h1 ? v1  : cap1;                    \
            capE0 = h0 ? cum : capE0; capE1 = h1 ? cum : capE1;                   \
        }                                                                         \
    }

    // one 8-step block: consumes ELC/EBC, loads block (g+2) into ELN/EBN
    #define CTC_BLOCK(TB_, ELCN, EBCN, ELN, EBN)                                  \
    {                                                                             \
        const int  cumP  = __shfl_up_sync(FULLM, cum, 1);                         \
        int        db    = cumP - cum;                                            \
        const bool adopt = (lane > 0) && (db > 40);                               \
        a0 = adopt ? 0.0f : a0;  a1 = adopt ? 0.0f : a1;                          \
        a2 = adopt ? 0.0f : a2;  a3 = adopt ? 0.0f : a3;                          \
        a4 = adopt ? 0.0f : a4;  a5 = adopt ? 0.0f : a5;                          \
        a6 = adopt ? 0.0f : a6;  a7 = adopt ? 0.0f : a7;                          \
        C  = adopt ? 0.0f : C;                                                    \
        cum = adopt ? cumP : cum;                                                 \
        db  = adopt ? 0 : db;                                                     \
        db  = (db < -126) ? -126 : db;                                            \
        const float bscale = __uint_as_float((unsigned)(127 + db) << 23);         \
        const float bs0    = (lane == 0) ? 0.0f : bscale;                         \
        b7pipe = __shfl_up_sync(FULLM, a7, 1);    /* re-seed pipeline */          \
        const float* rblk  = Eb + (size_t)((TB_) + 16) * EST;                     \
        _Pragma("unroll")                                                         \
        for (int k_ = 0; k_ < 8; ++k_) {                                          \
            ELN[k_] = __ldg((const float4*)(rblk + k_ * EST) + lane);             \
            EBN[k_] = __ldg(rblk + k_ * EST + 128);                               \
        }                                                                         \
        if ((unsigned)(tcap - (TB_)) < 8u) {                                      \
            _Pragma("unroll")                                                     \
            for (int k_ = 0; k_ < 8; ++k_)                                        \
                CTC_STEP(k_, TB_, bs0, ELCN, EBCN, true)                          \
        } else {                                                                  \
            _Pragma("unroll")                                                     \
            for (int k_ = 0; k_ < 8; ++k_)                                        \
                CTC_STEP(k_, TB_, bs0, ELCN, EBCN, false)                         \
        }                                                                         \
        const float mx = fmaxf(fmaxf(fmaxf(a0, a1), fmaxf(a2, a3)),               \
                               fmaxf(fmaxf(a4, a5), fmaxf(a6, fmaxf(a7, C))));    \
        const int ee   = (int)((__float_as_uint(mx) >> 23) & 0xffu);              \
        int radj = ee - 127;                                                      \
        radj = (radj < -90) ? -90 : radj;                                         \
        radj = (radj > 120) ? 120 : radj;                                         \
        const float sf = __uint_as_float((unsigned)(127 - radj) << 23);           \
        a0*=sf; a1*=sf; a2*=sf; a3*=sf; a4*=sf; a5*=sf; a6*=sf; a7*=sf; C*=sf;    \
        cum += radj;                                                              \
    }

    // ---- main: 128 blocks (t = 1..1024; t=1024 is harmless overshoot) ----
    // 42 triples + 2 tail blocks; block g consumes buffer g%3, loads g+2.
    for (int g3 = 0; g3 < 126; g3 += 3) {
        const int tb = 1 + 8 * g3;
        CTC_BLOCK(tb,      elA, ebA, elC, ebC)
        CTC_BLOCK(tb + 8,  elB, ebB, elA, ebA)
        CTC_BLOCK(tb + 16, elC, ebC, elB, ebB)
    }
    CTC_BLOCK(1009, elA, ebA, elC, ebC)   // block 126 (loads rows 1025..1032: zero pad)
    CTC_BLOCK(1017, elB, ebB, elA, ebA)   // block 127 (loads rows 1033..1040: zero pad)
    #undef CTC_STEP
    #undef CTC_BLOCK

    // ---- finish ----
    if (own0) { fin[0] = cap0; finE[0] = capE0; }
    if (own1) { fin[1] = cap1; finE[1] = capE1; }
    __syncwarp();

    if (lane == 0) {
        const float l0 = lg2f(fin[0]) + (float)finE[0];
        const float l1 = lg2f(fin[1]) + (float)finE[1];
        const float ll = lse2log(l0, l1) * LN2;
        g_loss[b] = -ll / (float)llen;
        __threadfence();
        const int old = atomicAdd(&g_ctr, 1);
        if (old == B - 1) {
            __threadfence();
            float s = 0.0f;
            #pragma unroll 8
            for (int i = 0; i < B; ++i) s += g_loss[i];
            *out = s * (1.0f / (float)B);
            g_ctr = 0;   // reset for next graph replay
        }
    }
}

extern "C" void kernel_launch(void* const* d_in, const int* in_sizes, int n_in,
                              void* d_out, int out_size) {
    const float* outputs        = (const float*)d_in[0];
    const int*   labels         = (const int*)d_in[1];
    const int*   output_lengths = (const int*)d_in[2];
    const int*   label_lengths  = (const int*)d_in[3];
    float* out = (float*)d_out;

    emit_exp<<<B * (T / 8), 256>>>(outputs, labels);
    ctc_rec<<<B, 32>>>(labels, output_lengths, label_lengths, out);
}

// round 14
// speedup vs baseline: 5.3720x; 1.0211x over previous
#include <cuda_runtime.h>
#include <cstdint>

constexpr int B = 64;
constexpr int T = 1024;
constexpr int V = 512;
constexpr int L = 128;
constexpr int EST  = 128;    // emit row stride: r[0..127] (ratio emits), power of 2
constexpr int TPAD = T + 32; // padded rows; overshoot rows stay zero (harmless)

#define FULLM  0xffffffffu
#define LOG2E  1.4426950408889634f
#define LN2    0.6931471805599453f

__device__ __align__(16) float Eexp[(size_t)B * TPAD * EST];   // ~34.6 MB, zero-init
__device__ float lb2arr[(size_t)B * T];                        // per-row log2(blank)
__device__ float g_loss[B];
__device__ int   g_ctr = 0;

__device__ __forceinline__ float ex2f(float x) {
    float y; asm("ex2.approx.f32 %0, %1;" : "=f"(y) : "f"(x)); return y;
}
__device__ __forceinline__ float lg2f(float x) {
    float y; asm("lg2.approx.f32 %0, %1;" : "=f"(y) : "f"(x)); return y;
}
__device__ __forceinline__ float lse2log(float a, float b) {
    const float m  = fmaxf(a, b);
    const float mn = fminf(a, b);
    return m + lg2f(1.0f + ex2f(mn - m));
}

// ---- Kernel 1: Eexp[b][t][li] = exp(logit[lab]-logit[blank]); lb2arr = blank*log2e --
__global__ __launch_bounds__(256)
void emit_exp(const float* __restrict__ outputs, const int* __restrict__ labels) {
    __shared__ int lab[L];
    const int nblk = T / 8;
    const int b   = blockIdx.x / nblk;
    const int t0  = (blockIdx.x % nblk) * 8;
    const int tid = threadIdx.x;

    if (tid < L) lab[tid] = __ldg(labels + b * L + tid);
    __syncthreads();

    const int li   = tid & 127;
    const int half = tid >> 7;
    const int colv = lab[li];

    #pragma unroll
    for (int r2 = 0; r2 < 4; ++r2) {
        const int r = t0 + r2 * 2 + half;
        const float* row  = outputs + ((size_t)b * T + r) * V;
        float*       Erow = Eexp    + ((size_t)b * TPAD + r) * EST;
        const float bl = __ldg(row);
        Erow[li] = ex2f((__ldg(row + colv) - bl) * LOG2E);
        if (li == 0) lb2arr[(size_t)b * T + r] = bl * LOG2E;
    }
}

// ---- Kernel 2: single-warp linear recursion, blank factored out, per-lane scaling ---
__global__ __launch_bounds__(32, 1)
void ctc_rec(const int* __restrict__ labels,
             const int* __restrict__ output_lengths,
             const int* __restrict__ label_lengths,
             float* __restrict__ out) {
    __shared__ float fin[2];
    __shared__ int   finE[2];

    const int b    = blockIdx.x;
    const int lane = threadIdx.x;

    const int olen = output_lengths[b];
    const int llen = label_lengths[b];
    const int tcap = olen - 1;
    const int s0g  = 2 * llen - 1;           // odd
    const int s1g  = 2 * llen;               // even (or 256)

    const int* lb = labels + b * L;
    float s0, s1, s2, s3;                    // skip weights as 0/1 floats
    {
        const int li0 = 4 * lane;
        const int c0 = __ldg(lb + li0), c1 = __ldg(lb + li0 + 1);
        const int c2 = __ldg(lb + li0 + 2), c3 = __ldg(lb + li0 + 3);
        s0 = ((li0 > 0) && (c0 != __ldg(lb + li0 - 1))) ? 1.0f : 0.0f;
        s1 = (c1 != c0) ? 1.0f : 0.0f;
        s2 = (c2 != c1) ? 1.0f : 0.0f;
        s3 = (c3 != c2) ? 1.0f : 0.0f;
    }

    const bool o0_0 = (s0g == 8 * lane + 1), o0_1 = (s0g == 8 * lane + 3);
    const bool o0_2 = (s0g == 8 * lane + 5), o0_3 = (s0g == 8 * lane + 7);
    const bool o1_0 = (s1g == 8 * lane),     o1_1 = (s1g == 8 * lane + 2);
    const bool o1_2 = (s1g == 8 * lane + 4), o1_3 = (s1g == 8 * lane + 6);
    const bool oC   = (lane == 31) && (s1g == 256);
    const bool own0 = o0_0 || o0_1 || o0_2 || o0_3;
    const bool own1 = o1_0 || o1_1 || o1_2 || o1_3 || oC;

    const float* Eb = Eexp + (size_t)b * TPAD * EST;

    // ---- t = 0 (scaled by 2^-32 for renorm headroom; cum starts at 32) ----
    float a0=0,a1=0,a2=0,a3=0,a4=0,a5=0,a6=0,a7=0, C=0;
    int   cum = 32;
    float cap0 = 1.0f, cap1 = 1.0f;
    int   capE0 = 0, capE1 = 0;
    {
        const float h = __uint_as_float((unsigned)(127 - 32) << 23);   // 2^-32
        const float r0 = __ldg(Eb + 0);
        if (lane == 0) { a0 = h; a1 = r0 * h; }
        if (tcap == 0) {
            cap0 = o0_0 ? a1 : cap0;
            cap1 = o1_0 ? a0 : cap1;
            capE0 = cum; capE1 = cum;
        }
    }

    // triple-buffered emit registers; each buffer holds one 8-row block
    float4 elA[8], elB[8], elC[8];
    #pragma unroll
    for (int k = 0; k < 8; ++k) {       // preload block 0 (rows 1..8) into A
        elA[k] = __ldg((const float4*)(Eb + (size_t)(1 + k) * EST) + lane);
    }
    #pragma unroll
    for (int k = 0; k < 8; ++k) {       // preload block 1 (rows 9..16) into B
        elB[k] = __ldg((const float4*)(Eb + (size_t)(9 + k) * EST) + lane);
    }

    float b7pipe = 0.0f;                 // pipelined boundary shfl value

    // one recursion step consuming buffer ELC slot K_
    #define CTC_STEP(K_, TB_, BS0_, ELC, CAPF_)                                   \
    {                                                                             \
        const float b7n = b7pipe * (BS0_);    /* shfl issued last step */         \
        const float4 e4 = ELC[K_];                                                \
        C  = C + a7;                                                              \
        const float a7n = (a7 + fmaf(s3, a5, a6)) * e4.w;                         \
        b7pipe = __shfl_up_sync(FULLM, a7n, 1);   /* for next step */             \
        a6 = a6 + a5;                                                             \
        a5 = (a5 + fmaf(s2, a3, a4 )) * e4.z;                                     \
        a4 = a4 + a3;                                                             \
        a3 = (a3 + fmaf(s1, a1, a2 )) * e4.y;                                     \
        a2 = a2 + a1;                                                             \
        a1 = (a1 + fmaf(s0, b7n, a0)) * e4.x;                                     \
        a0 = a0 + b7n;                                                            \
        a7 = a7n;                                                                 \
        if (CAPF_) {                                                              \
            const bool pc  = ((TB_) + (K_) == tcap);                              \
            const bool h0  = pc && own0;                                          \
            const bool h1  = pc && own1;                                          \
            const float v0 = o0_0 ? a1 : (o0_1 ? a3 : (o0_2 ? a5 : a7));          \
            const float v1 = o1_0 ? a0 : (o1_1 ? a2 :                             \
                             (o1_2 ? a4 : (oC ? C : a6)));                        \
            cap0  = h0 ? v0  : cap0;  cap1  = h1 ? v1  : cap1;                    \
            capE0 = h0 ? cum : capE0; capE1 = h1 ? cum : capE1;                   \
        }                                                                         \
    }

    // one 8-step block: consumes ELCN, loads block (g+2) into ELN
    #define CTC_BLOCK(TB_, ELCN, ELN)                                             \
    {                                                                             \
        const int  cumP  = __shfl_up_sync(FULLM, cum, 1);                         \
        int        db    = cumP - cum;                                            \
        const bool adopt = (lane > 0) && (db > 40);                               \
        a0 = adopt ? 0.0f : a0;  a1 = adopt ? 0.0f : a1;                          \
        a2 = adopt ? 0.0f : a2;  a3 = adopt ? 0.0f : a3;                          \
        a4 = adopt ? 0.0f : a4;  a5 = adopt ? 0.0f : a5;                          \
        a6 = adopt ? 0.0f : a6;  a7 = adopt ? 0.0f : a7;                          \
        C  = adopt ? 0.0f : C;                                                    \
        cum = adopt ? cumP : cum;                                                 \
        db  = adopt ? 0 : db;                                                     \
        db  = (db < -126) ? -126 : db;                                            \
        const float bscale = __uint_as_float((unsigned)(127 + db) << 23);         \
        const float bs0    = (lane == 0) ? 0.0f : bscale;                         \
        b7pipe = __shfl_up_sync(FULLM, a7, 1);    /* re-seed pipeline */          \
        const float* rblk  = Eb + (size_t)((TB_) + 16) * EST;                     \
        _Pragma("unroll")                                                         \
        for (int k_ = 0; k_ < 8; ++k_)                                            \
            ELN[k_] = __ldg((const float4*)(rblk + k_ * EST) + lane);             \
        if ((unsigned)(tcap - (TB_)) < 8u) {                                      \
            _Pragma("unroll")                                                     \
            for (int k_ = 0; k_ < 8; ++k_)                                        \
                CTC_STEP(k_, TB_, bs0, ELCN, true)                                \
        } else {                                                                  \
            _Pragma("unroll")                                                     \
            for (int k_ = 0; k_ < 8; ++k_)                                        \
                CTC_STEP(k_, TB_, bs0, ELCN, false)                               \
        }                                                                         \
        /* renorm to max in [2^-32, 2^-31): 8-step worst growth stays finite */   \
        const float mx = fmaxf(fmaxf(fmaxf(a0, a1), fmaxf(a2, a3)),               \
                               fmaxf(fmaxf(a4, a5), fmaxf(a6, fmaxf(a7, C))));    \
        const int ee   = (int)((__float_as_uint(mx) >> 23) & 0xffu);              \
        int radj = ee - 95;                                                       \
        radj = (radj < -95) ? -95 : radj;                                         \
        radj = (radj > 126) ? 126 : radj;                                         \
        const float sf = __uint_as_float((unsigned)(127 - radj) << 23);           \
        a0*=sf; a1*=sf; a2*=sf; a3*=sf; a4*=sf; a5*=sf; a6*=sf; a7*=sf; C*=sf;    \
        cum += radj;                                                              \
    }

    // ---- main: 128 blocks (t = 1..1024; t=1024 is harmless overshoot) ----
    for (int g3 = 0; g3 < 126; g3 += 3) {
        const int tb = 1 + 8 * g3;
        CTC_BLOCK(tb,      elA, elC)
        CTC_BLOCK(tb + 8,  elB, elA)
        CTC_BLOCK(tb + 16, elC, elB)
    }
    CTC_BLOCK(1009, elA, elC)   // block 126 (loads zero-padded rows)
    CTC_BLOCK(1017, elB, elA)   // block 127 (loads zero-padded rows)
    #undef CTC_STEP
    #undef CTC_BLOCK

    // ---- epilogue: recover sum of factored-out blank logs (deterministic order) ----
    float S = 0.0f;
    {
        const float* lbp = lb2arr + (size_t)b * T;
        #pragma unroll 8
        for (int i = lane; i < T; i += 32)
            S += (i <= tcap) ? __ldg(lbp + i) : 0.0f;
        #pragma unroll
        for (int o = 16; o > 0; o >>= 1)
            S += __shfl_xor_sync(FULLM, S, o);
    }

    if (own0) { fin[0] = cap0; finE[0] = capE0; }
    if (own1) { fin[1] = cap1; finE[1] = capE1; }
    __syncwarp();

    if (lane == 0) {
        const float l0 = lg2f(fin[0]) + (float)finE[0] + S;
        const float l1 = lg2f(fin[1]) + (float)finE[1] + S;
        const float ll = lse2log(l0, l1) * LN2;
        g_loss[b] = -ll / (float)llen;
        __threadfence();
        const int old = atomicAdd(&g_ctr, 1);
        if (old == B - 1) {
            __threadfence();
            float s = 0.0f;
            #pragma unroll 8
            for (int i = 0; i < B; ++i) s += g_loss[i];
            *out = s * (1.0f / (float)B);
            g_ctr = 0;   // reset for next graph replay
        }
    }
}

extern "C" void kernel_launch(void* const* d_in, const int* in_sizes, int n_in,
                              void* d_out, int out_size) {
    const float* outputs        = (const float*)d_in[0];
    const int*   labels         = (const int*)d_in[1];
    const int*   output_lengths = (const int*)d_in[2];
    const int*   label_lengths  = (const int*)d_in[3];
    float* out = (float*)d_out;

    emit_exp<<<B * (T / 8), 256>>>(outputs, labels);
    ctc_rec<<<B, 32>>>(labels, output_lengths, label_lengths, out);
}